// round 1
// baseline (speedup 1.0000x reference)
#include <cuda_runtime.h>

// Problem constants (fixed by the reference)
#define NPIX (512 * 512)
#define RB 6                 // d+1 for bilateral (d=5)
#define RS 3                 // d+1 for spatial  (d=2)
#define MAXVB (RB * NPIX + 2)
#define MAXVS (RS * NPIX + 2)
#define ALPHA_B 0.9696969696969697f   // 1/(1+2^-5)
#define ALPHA_S 0.8f                  // 1/(1+2^-2)
#define BI_COMPAT 10.0f
#define SP_COMPAT 3.0f

// Static device scratch (no runtime allocation allowed)
__device__ float4 g_tabB[2][MAXVB];
__device__ float4 g_tabS[2][MAXVS];
__device__ float4 g_Q[2][NPIX];
__device__ float  g_invB[NPIX];
__device__ float  g_invS[NPIX];

// ---------------------------------------------------------------------------
// Q0 = softmax(-unary)
__global__ void k_init(const float4* __restrict__ u4, float4* __restrict__ Q) {
    int n = blockIdx.x * blockDim.x + threadIdx.x;
    if (n >= NPIX) return;
    float4 u = u4[n];
    float x0 = -u.x, x1 = -u.y, x2 = -u.z, x3 = -u.w;
    float m = fmaxf(fmaxf(x0, x1), fmaxf(x2, x3));
    float e0 = __expf(x0 - m), e1 = __expf(x1 - m);
    float e2 = __expf(x2 - m), e3 = __expf(x3 - m);
    float inv = 1.0f / (e0 + e1 + e2 + e3);
    Q[n] = make_float4(e0 * inv, e1 * inv, e2 * inv, e3 * inv);
}

// ---------------------------------------------------------------------------
// Splat: scatter-add pixel values into lattice table (1-based vertex ids).
// vals == nullptr means "ones" (normalizer filter).
template <int R>
__global__ void k_splat(const float* __restrict__ ws, const int* __restrict__ os,
                        const float4* __restrict__ vals, float4* __restrict__ tab) {
    int n = blockIdx.x * blockDim.x + threadIdx.x;
    if (n >= NPIX) return;
    float4 v = vals ? vals[n] : make_float4(1.f, 1.f, 1.f, 1.f);
#pragma unroll
    for (int r = 0; r < R; r++) {
        float w = ws[n * R + r];
        int o = os[n * R + r];
        float* t = reinterpret_cast<float*>(tab + o);
        atomicAdd(t + 0, v.x * w);
        atomicAdd(t + 1, v.y * w);
        atomicAdd(t + 2, v.z * w);
        atomicAdd(t + 3, v.w * w);
    }
}

// ---------------------------------------------------------------------------
// One blur pass (functional: reads old table, writes new table).
// Vertex i (1..M): out[i] = in[i] + 0.5*(in[bn0] + in[bn1]); row 0 stays zero.
__global__ void k_blur(const float4* __restrict__ in, float4* __restrict__ out,
                       const int2* __restrict__ bn, int M) {
    int i = blockIdx.x * blockDim.x + threadIdx.x;
    if (i >= M) return;
    if (i == 0) out[0] = make_float4(0.f, 0.f, 0.f, 0.f);
    int2 nb = bn[i];
    float4 a = in[i + 1];
    float4 b = in[nb.x];
    float4 c = in[nb.y];
    out[i + 1] = make_float4(a.x + 0.5f * (b.x + c.x),
                             a.y + 0.5f * (b.y + c.y),
                             a.z + 0.5f * (b.z + c.z),
                             a.w + 0.5f * (b.w + c.w));
}

// ---------------------------------------------------------------------------
// Normalizer slice: inv[n] = 1/(alpha * sum_r tab[os].x * ws + 1e-20)
template <int R>
__global__ void k_norm(const float4* __restrict__ tab, const float* __restrict__ ws,
                       const int* __restrict__ os, float alpha, float* __restrict__ inv) {
    int n = blockIdx.x * blockDim.x + threadIdx.x;
    if (n >= NPIX) return;
    float s = 0.f;
#pragma unroll
    for (int r = 0; r < R; r++) {
        s = fmaf(tab[os[n * R + r]].x, ws[n * R + r], s);
    }
    inv[n] = 1.0f / (alpha * s + 1e-20f);
}

// ---------------------------------------------------------------------------
// Fused: slice both lattices, combine messages, softmax update of Q.
__global__ void k_fused(const float4* __restrict__ u4,
                        const float4* __restrict__ tB, const float* __restrict__ wsB,
                        const int* __restrict__ osB, const float* __restrict__ invB,
                        const float4* __restrict__ tS, const float* __restrict__ wsS,
                        const int* __restrict__ osS, const float* __restrict__ invS,
                        float4* __restrict__ Qout) {
    int n = blockIdx.x * blockDim.x + threadIdx.x;
    if (n >= NPIX) return;

    float4 fb = make_float4(0.f, 0.f, 0.f, 0.f);
#pragma unroll
    for (int r = 0; r < RB; r++) {
        int o = osB[n * RB + r];
        float w = wsB[n * RB + r];
        float4 t = tB[o];
        fb.x = fmaf(t.x, w, fb.x);
        fb.y = fmaf(t.y, w, fb.y);
        fb.z = fmaf(t.z, w, fb.z);
        fb.w = fmaf(t.w, w, fb.w);
    }
    float cb = BI_COMPAT * ALPHA_B * invB[n];

    float4 fs = make_float4(0.f, 0.f, 0.f, 0.f);
#pragma unroll
    for (int r = 0; r < RS; r++) {
        int o = osS[n * RS + r];
        float w = wsS[n * RS + r];
        float4 t = tS[o];
        fs.x = fmaf(t.x, w, fs.x);
        fs.y = fmaf(t.y, w, fs.y);
        fs.z = fmaf(t.z, w, fs.z);
        fs.w = fmaf(t.w, w, fs.w);
    }
    float cs = SP_COMPAT * ALPHA_S * invS[n];

    float4 u = u4[n];
    // x = -u + msg   (COMPATIBILITY = -1)
    float x0 = fmaf(fb.x, cb, fmaf(fs.x, cs, -u.x));
    float x1 = fmaf(fb.y, cb, fmaf(fs.y, cs, -u.y));
    float x2 = fmaf(fb.z, cb, fmaf(fs.z, cs, -u.z));
    float x3 = fmaf(fb.w, cb, fmaf(fs.w, cs, -u.w));

    float m = fmaxf(fmaxf(x0, x1), fmaxf(x2, x3));
    float e0 = __expf(x0 - m), e1 = __expf(x1 - m);
    float e2 = __expf(x2 - m), e3 = __expf(x3 - m);
    float inv = 1.0f / (e0 + e1 + e2 + e3);
    Qout[n] = make_float4(e0 * inv, e1 * inv, e2 * inv, e3 * inv);
}

// ---------------------------------------------------------------------------
extern "C" void kernel_launch(void* const* d_in, const int* in_sizes, int n_in,
                              void* d_out, int out_size) {
    // Inputs in metadata order:
    // 0 unary[N,4] f32, 1 ws_b[N,6] f32, 2 os_b[N,6] i32, 3 bn_b[6,Mb,2] i32,
    // 4 M_b scalar, 5 ws_s[N,3] f32, 6 os_s[N,3] i32, 7 bn_s[3,Ms,2] i32, 8 M_s scalar
    const float4* u4  = (const float4*)d_in[0];
    const float*  wsB = (const float*)d_in[1];
    const int*    osB = (const int*)d_in[2];
    const int*    bnB = (const int*)d_in[3];
    const float*  wsS = (const float*)d_in[5];
    const int*    osS = (const int*)d_in[6];
    const int*    bnS = (const int*)d_in[7];

    const int Mb = in_sizes[3] / (2 * RB);   // bn_b has 6*Mb*2 ints
    const int Ms = in_sizes[7] / (2 * RS);   // bn_s has 3*Ms*2 ints

    float4 *tabB, *tabS, *Qbuf;
    float *invB, *invS;
    cudaGetSymbolAddress((void**)&tabB, g_tabB);
    cudaGetSymbolAddress((void**)&tabS, g_tabS);
    cudaGetSymbolAddress((void**)&Qbuf, g_Q);
    cudaGetSymbolAddress((void**)&invB, g_invB);
    cudaGetSymbolAddress((void**)&invS, g_invS);
    float4* tB[2] = { tabB, tabB + MAXVB };
    float4* tS[2] = { tabS, tabS + MAXVS };
    float4* Q[2]  = { Qbuf, Qbuf + NPIX };

    const int TPB = 256;
    const int GN  = (NPIX + TPB - 1) / TPB;
    const int GMb = (Mb + TPB - 1) / TPB;
    const int GMs = (Ms + TPB - 1) / TPB;

    // Q0 = softmax(-u)
    k_init<<<GN, TPB>>>(u4, Q[0]);

    // Normalizer for bilateral lattice (filter of ones, channel .x used)
    cudaMemsetAsync(tB[0], 0, (size_t)(Mb + 1) * sizeof(float4));
    k_splat<RB><<<GN, TPB>>>(wsB, osB, nullptr, tB[0]);
    int cb = 0;
    for (int j = 0; j < RB; j++) {
        k_blur<<<GMb, TPB>>>(tB[cb], tB[1 - cb], (const int2*)(bnB + (size_t)j * 2 * Mb), Mb);
        cb ^= 1;
    }
    k_norm<RB><<<GN, TPB>>>(tB[cb], wsB, osB, ALPHA_B, invB);

    // Normalizer for spatial lattice
    cudaMemsetAsync(tS[0], 0, (size_t)(Ms + 1) * sizeof(float4));
    k_splat<RS><<<GN, TPB>>>(wsS, osS, nullptr, tS[0]);
    int cs = 0;
    for (int j = 0; j < RS; j++) {
        k_blur<<<GMs, TPB>>>(tS[cs], tS[1 - cs], (const int2*)(bnS + (size_t)j * 2 * Ms), Ms);
        cs ^= 1;
    }
    k_norm<RS><<<GN, TPB>>>(tS[cs], wsS, osS, ALPHA_S, invS);

    // 10 mean-field iterations
    int q = 0;
    for (int it = 0; it < 10; it++) {
        cudaMemsetAsync(tB[0], 0, (size_t)(Mb + 1) * sizeof(float4));
        k_splat<RB><<<GN, TPB>>>(wsB, osB, Q[q], tB[0]);
        cb = 0;
        for (int j = 0; j < RB; j++) {
            k_blur<<<GMb, TPB>>>(tB[cb], tB[1 - cb], (const int2*)(bnB + (size_t)j * 2 * Mb), Mb);
            cb ^= 1;
        }

        cudaMemsetAsync(tS[0], 0, (size_t)(Ms + 1) * sizeof(float4));
        k_splat<RS><<<GN, TPB>>>(wsS, osS, Q[q], tS[0]);
        cs = 0;
        for (int j = 0; j < RS; j++) {
            k_blur<<<GMs, TPB>>>(tS[cs], tS[1 - cs], (const int2*)(bnS + (size_t)j * 2 * Ms), Ms);
            cs ^= 1;
        }

        float4* outp = (it == 9) ? (float4*)d_out : Q[1 - q];
        k_fused<<<GN, TPB>>>(u4, tB[cb], wsB, osB, invB,
                             tS[cs], wsS, osS, invS, outp);
        q ^= 1;
    }
}

// round 2
// speedup vs baseline: 2.4647x; 2.4647x over previous
#include <cuda_runtime.h>

#define NPIX (512 * 512)
#define RB 6
#define RS 3
#define MAXVB (RB * NPIX + 2)
#define MAXVS (RS * NPIX + 2)
#define ALPHA_B 0.9696969696969697f   // 1/(1+2^-5)
#define ALPHA_S 0.8f                  // 1/(1+2^-2)
#define TPB 256
#define ITEMS 4
#define CHUNK (TPB * ITEMS)

// ---- static device scratch (no runtime allocation) ----
__device__ float4 g_SB[MAXVB];        // bilateral splat buffer
__device__ float4 g_PB[2][MAXVB];     // bilateral blur ping-pong
__device__ float4 g_SS[MAXVS];        // spatial splat buffer
__device__ float4 g_PS[2][MAXVS];     // spatial blur ping-pong
__device__ float  g_nB[2][MAXVB];     // scalar normalizer tables (bilateral)
__device__ float  g_nS[2][MAXVS];     // scalar normalizer tables (spatial)
__device__ float  g_coefB[NPIX];
__device__ float  g_coefS[NPIX];

__device__ __forceinline__ void red_v4(float4* p, float4 v) {
    asm volatile("red.global.add.v4.f32 [%0], {%1,%2,%3,%4};"
                 :: "l"(p), "f"(v.x), "f"(v.y), "f"(v.z), "f"(v.w) : "memory");
}

// ---------------------------------------------------------------------------
// One-time: splat ones into both scalar normalizer tables.
__global__ void k_splat1(const float* __restrict__ wsB, const int* __restrict__ osB,
                         const float* __restrict__ wsS, const int* __restrict__ osS,
                         float* __restrict__ tB, float* __restrict__ tS) {
    int n = blockIdx.x * blockDim.x + threadIdx.x;
    if (n >= NPIX) return;
#pragma unroll
    for (int r = 0; r < RB; r++) atomicAdd(tB + osB[n * RB + r], wsB[n * RB + r]);
#pragma unroll
    for (int r = 0; r < RS; r++) atomicAdd(tS + osS[n * RS + r], wsS[n * RS + r]);
}

// ---------------------------------------------------------------------------
// Scalar blur pass over both lattices (spatial side optional).
__global__ void k_blur1_both(const float* __restrict__ inB, float* __restrict__ outB,
                             const int2* __restrict__ bnB, int Mb, int nBlkB,
                             const float* __restrict__ inS, float* __restrict__ outS,
                             const int2* __restrict__ bnS, int Ms) {
    int blk = blockIdx.x;
    const float* in; float* out; const int2* bn; int M;
    bool first;
    if (blk < nBlkB) { in = inB; out = outB; bn = bnB; M = Mb; first = (blk == 0); }
    else { blk -= nBlkB; in = inS; out = outS; bn = bnS; M = Ms; first = (blk == 0); }

    int base = blk * CHUNK + threadIdx.x;
    int2 nb[ITEMS];
#pragma unroll
    for (int k = 0; k < ITEMS; k++) {
        int i = base + k * TPB;
        nb[k] = (i < M) ? bn[i] : make_int2(0, 0);
    }
    float a[ITEMS], b[ITEMS], c[ITEMS];
#pragma unroll
    for (int k = 0; k < ITEMS; k++) {
        int i = base + k * TPB;
        a[k] = (i < M) ? in[i + 1] : 0.f;
        b[k] = in[nb[k].x];
        c[k] = in[nb[k].y];
    }
#pragma unroll
    for (int k = 0; k < ITEMS; k++) {
        int i = base + k * TPB;
        if (i < M) out[i + 1] = a[k] + 0.5f * (b[k] + c[k]);
    }
    if (first && threadIdx.x == 0) out[0] = 0.f;
}

// ---------------------------------------------------------------------------
// float4 blur pass over both lattices, plus optional zeroing blocks that clear
// the next splat buffers (used on pass j==1; safe: pass 0 already consumed them).
__global__ void k_blur4_both(const float4* __restrict__ inB, float4* __restrict__ outB,
                             const int2* __restrict__ bnB, int Mb, int nBlkB,
                             const float4* __restrict__ inS, float4* __restrict__ outS,
                             const int2* __restrict__ bnS, int Ms, int nBlkS,
                             float4* __restrict__ z0, int nz0,
                             float4* __restrict__ z1, int nz1, int nBlkZ) {
    int blk = blockIdx.x;
    if (blk >= nBlkB + nBlkS) {
        // zeroing role
        int zb = blk - nBlkB - nBlkS;
        int stride = nBlkZ * TPB;
        for (int i = zb * TPB + threadIdx.x; i < nz0; i += stride)
            z0[i] = make_float4(0.f, 0.f, 0.f, 0.f);
        for (int i = zb * TPB + threadIdx.x; i < nz1; i += stride)
            z1[i] = make_float4(0.f, 0.f, 0.f, 0.f);
        return;
    }
    const float4* in; float4* out; const int2* bn; int M;
    bool first;
    if (blk < nBlkB) { in = inB; out = outB; bn = bnB; M = Mb; first = (blk == 0); }
    else { blk -= nBlkB; in = inS; out = outS; bn = bnS; M = Ms; first = (blk == 0); }

    int base = blk * CHUNK + threadIdx.x;
    int2 nb[ITEMS];
#pragma unroll
    for (int k = 0; k < ITEMS; k++) {
        int i = base + k * TPB;
        nb[k] = (i < M) ? bn[i] : make_int2(0, 0);
    }
    float4 a[ITEMS], b[ITEMS], c[ITEMS];
#pragma unroll
    for (int k = 0; k < ITEMS; k++) {
        int i = base + k * TPB;
        a[k] = (i < M) ? in[i + 1] : make_float4(0.f, 0.f, 0.f, 0.f);
        b[k] = in[nb[k].x];
        c[k] = in[nb[k].y];
    }
#pragma unroll
    for (int k = 0; k < ITEMS; k++) {
        int i = base + k * TPB;
        if (i < M)
            out[i + 1] = make_float4(a[k].x + 0.5f * (b[k].x + c[k].x),
                                     a[k].y + 0.5f * (b[k].y + c[k].y),
                                     a[k].z + 0.5f * (b[k].z + c[k].z),
                                     a[k].w + 0.5f * (b[k].w + c[k].w));
    }
    if (first && threadIdx.x == 0) out[0] = make_float4(0.f, 0.f, 0.f, 0.f);
}

// ---------------------------------------------------------------------------
// One-time: slice normalizer tables -> per-pixel message coefficients,
// then Q0 = softmax(-u) splatted directly into the float4 splat buffers.
__global__ void k_norm_init(const float* __restrict__ nBf, const float* __restrict__ nSf,
                            const float* __restrict__ wsB, const int* __restrict__ osB,
                            const float* __restrict__ wsS, const int* __restrict__ osS,
                            const float4* __restrict__ u4,
                            float* __restrict__ coefB, float* __restrict__ coefS,
                            float4* __restrict__ SB, float4* __restrict__ SS) {
    int n = blockIdx.x * blockDim.x + threadIdx.x;
    if (n >= NPIX) return;
    float sB = 0.f;
#pragma unroll
    for (int r = 0; r < RB; r++)
        sB = fmaf(nBf[osB[n * RB + r]], wsB[n * RB + r], sB);
    coefB[n] = 10.0f * ALPHA_B / (ALPHA_B * sB + 1e-20f);
    float sS = 0.f;
#pragma unroll
    for (int r = 0; r < RS; r++)
        sS = fmaf(nSf[osS[n * RS + r]], wsS[n * RS + r], sS);
    coefS[n] = 3.0f * ALPHA_S / (ALPHA_S * sS + 1e-20f);

    float4 u = u4[n];
    float x0 = -u.x, x1 = -u.y, x2 = -u.z, x3 = -u.w;
    float m = fmaxf(fmaxf(x0, x1), fmaxf(x2, x3));
    float e0 = __expf(x0 - m), e1 = __expf(x1 - m);
    float e2 = __expf(x2 - m), e3 = __expf(x3 - m);
    float inv = 1.0f / (e0 + e1 + e2 + e3);
    float4 q = make_float4(e0 * inv, e1 * inv, e2 * inv, e3 * inv);

#pragma unroll
    for (int r = 0; r < RB; r++) {
        float w = wsB[n * RB + r];
        red_v4(SB + osB[n * RB + r], make_float4(q.x * w, q.y * w, q.z * w, q.w * w));
    }
#pragma unroll
    for (int r = 0; r < RS; r++) {
        float w = wsS[n * RS + r];
        red_v4(SS + osS[n * RS + r], make_float4(q.x * w, q.y * w, q.z * w, q.w * w));
    }
}

// ---------------------------------------------------------------------------
// Per-iteration: slice both blurred tables, message + softmax, then either
// splat the new Q into the (pre-zeroed) splat buffers or write final output.
__global__ void k_fused(const float4* __restrict__ tB, const float4* __restrict__ tS,
                        const float* __restrict__ wsB, const int* __restrict__ osB,
                        const float* __restrict__ wsS, const int* __restrict__ osS,
                        const float* __restrict__ coefB, const float* __restrict__ coefS,
                        const float4* __restrict__ u4,
                        float4* __restrict__ SB, float4* __restrict__ SS,
                        float4* __restrict__ outQ, int write_out) {
    int n = blockIdx.x * blockDim.x + threadIdx.x;
    if (n >= NPIX) return;

    float4 fb = make_float4(0.f, 0.f, 0.f, 0.f);
#pragma unroll
    for (int r = 0; r < RB; r++) {
        float w = wsB[n * RB + r];
        float4 t = tB[osB[n * RB + r]];
        fb.x = fmaf(t.x, w, fb.x); fb.y = fmaf(t.y, w, fb.y);
        fb.z = fmaf(t.z, w, fb.z); fb.w = fmaf(t.w, w, fb.w);
    }
    float4 fs = make_float4(0.f, 0.f, 0.f, 0.f);
#pragma unroll
    for (int r = 0; r < RS; r++) {
        float w = wsS[n * RS + r];
        float4 t = tS[osS[n * RS + r]];
        fs.x = fmaf(t.x, w, fs.x); fs.y = fmaf(t.y, w, fs.y);
        fs.z = fmaf(t.z, w, fs.z); fs.w = fmaf(t.w, w, fs.w);
    }
    float cb = coefB[n];
    float cs = coefS[n];
    float4 u = u4[n];
    float x0 = fmaf(fb.x, cb, fmaf(fs.x, cs, -u.x));
    float x1 = fmaf(fb.y, cb, fmaf(fs.y, cs, -u.y));
    float x2 = fmaf(fb.z, cb, fmaf(fs.z, cs, -u.z));
    float x3 = fmaf(fb.w, cb, fmaf(fs.w, cs, -u.w));

    float m = fmaxf(fmaxf(x0, x1), fmaxf(x2, x3));
    float e0 = __expf(x0 - m), e1 = __expf(x1 - m);
    float e2 = __expf(x2 - m), e3 = __expf(x3 - m);
    float inv = 1.0f / (e0 + e1 + e2 + e3);
    float4 q = make_float4(e0 * inv, e1 * inv, e2 * inv, e3 * inv);

    if (write_out) {
        outQ[n] = q;
        return;
    }
#pragma unroll
    for (int r = 0; r < RB; r++) {
        float w = wsB[n * RB + r];
        red_v4(SB + osB[n * RB + r], make_float4(q.x * w, q.y * w, q.z * w, q.w * w));
    }
#pragma unroll
    for (int r = 0; r < RS; r++) {
        float w = wsS[n * RS + r];
        red_v4(SS + osS[n * RS + r], make_float4(q.x * w, q.y * w, q.z * w, q.w * w));
    }
}

// ---------------------------------------------------------------------------
extern "C" void kernel_launch(void* const* d_in, const int* in_sizes, int n_in,
                              void* d_out, int out_size) {
    const float4* u4  = (const float4*)d_in[0];
    const float*  wsB = (const float*)d_in[1];
    const int*    osB = (const int*)d_in[2];
    const int*    bnB = (const int*)d_in[3];
    const float*  wsS = (const float*)d_in[5];
    const int*    osS = (const int*)d_in[6];
    const int*    bnS = (const int*)d_in[7];

    const int Mb = in_sizes[3] / (2 * RB);
    const int Ms = in_sizes[7] / (2 * RS);

    float4 *SB, *PB, *SS, *PS;
    float *nB, *nS, *coefB, *coefS;
    cudaGetSymbolAddress((void**)&SB, g_SB);
    cudaGetSymbolAddress((void**)&PB, g_PB);
    cudaGetSymbolAddress((void**)&SS, g_SS);
    cudaGetSymbolAddress((void**)&PS, g_PS);
    cudaGetSymbolAddress((void**)&nB, g_nB);
    cudaGetSymbolAddress((void**)&nS, g_nS);
    cudaGetSymbolAddress((void**)&coefB, g_coefB);
    cudaGetSymbolAddress((void**)&coefS, g_coefS);
    float4* PBb[2] = { PB, PB + MAXVB };
    float4* PSb[2] = { PS, PS + MAXVS };
    float*  nBb[2] = { nB, nB + MAXVB };
    float*  nSb[2] = { nS, nS + MAXVS };

    const int GN    = (NPIX + TPB - 1) / TPB;
    const int nBlkB = (Mb + CHUNK - 1) / CHUNK;
    const int nBlkS = (Ms + CHUNK - 1) / CHUNK;
    const int nBlkZ = 64;

    // ---- one-time normalizer + init ----
    cudaMemsetAsync(nBb[0], 0, (size_t)(Mb + 1) * sizeof(float));
    cudaMemsetAsync(nSb[0], 0, (size_t)(Ms + 1) * sizeof(float));
    cudaMemsetAsync(SB, 0, (size_t)(Mb + 1) * sizeof(float4));
    cudaMemsetAsync(SS, 0, (size_t)(Ms + 1) * sizeof(float4));

    k_splat1<<<GN, TPB>>>(wsB, osB, wsS, osS, nBb[0], nSb[0]);
    for (int j = 0; j < RB; j++) {
        int sAct = (j < RS);
        k_blur1_both<<<nBlkB + (sAct ? nBlkS : 0), TPB>>>(
            nBb[j & 1], nBb[(j + 1) & 1], (const int2*)(bnB + (size_t)j * 2 * Mb), Mb, nBlkB,
            sAct ? nSb[j & 1] : nullptr, sAct ? nSb[(j + 1) & 1] : nullptr,
            sAct ? (const int2*)(bnS + (size_t)j * 2 * Ms) : nullptr, sAct ? Ms : 0);
    }
    // bilateral final in nBb[0] (6 passes), spatial final in nSb[1] (3 passes)
    k_norm_init<<<GN, TPB>>>(nBb[0], nSb[1], wsB, osB, wsS, osS, u4,
                             coefB, coefS, SB, SS);

    // ---- 10 mean-field iterations ----
    for (int it = 0; it < 10; it++) {
        for (int j = 0; j < RB; j++) {
            int sAct = (j < RS);
            const float4* ib = (j == 0) ? SB : PBb[(j - 1) & 1];
            float4* ob = PBb[j & 1];
            const float4* is = (j == 0) ? SS : PSb[(j - 1) & 1];
            float4* osp = PSb[j & 1];
            int zBlk = (j == 1) ? nBlkZ : 0;
            k_blur4_both<<<nBlkB + (sAct ? nBlkS : 0) + zBlk, TPB>>>(
                ib, ob, (const int2*)(bnB + (size_t)j * 2 * Mb), Mb, nBlkB,
                sAct ? is : nullptr, sAct ? osp : nullptr,
                sAct ? (const int2*)(bnS + (size_t)j * 2 * Ms) : nullptr,
                sAct ? Ms : 0, sAct ? nBlkS : 0,
                SB, Mb + 1, SS, Ms + 1, nBlkZ);
        }
        // bilateral final PBb[1], spatial final PSb[0]
        k_fused<<<GN, TPB>>>(PBb[1], PSb[0], wsB, osB, wsS, osS,
                             coefB, coefS, u4, SB, SS,
                             (float4*)d_out, (it == 9) ? 1 : 0);
    }
}

// round 3
// speedup vs baseline: 2.4982x; 1.0136x over previous
#include <cuda_runtime.h>

#define NPIX (512 * 512)
#define RB 6
#define RS 3
#define MAXVB (RB * NPIX + 2)
#define MAXVS (RS * NPIX + 2)
#define ALPHA_B 0.9696969696969697f   // 1/(1+2^-5)
#define ALPHA_S 0.8f                  // 1/(1+2^-2)
#define TPB 256

// ---- static device scratch (no runtime allocation) ----
__device__ float4 g_SB[MAXVB];        // bilateral splat buffer
__device__ float4 g_PB[2][MAXVB];     // bilateral blur ping-pong
__device__ float4 g_SS[MAXVS];        // spatial splat buffer
__device__ float4 g_PS[2][MAXVS];     // spatial blur ping-pong
__device__ float  g_nB[2][MAXVB];     // scalar normalizer tables (bilateral)
__device__ float  g_nS[2][MAXVS];     // scalar normalizer tables (spatial)
__device__ float  g_coefB[NPIX];
__device__ float  g_coefS[NPIX];

__device__ __forceinline__ void red_v4(float4* p, float4 v) {
    asm volatile("red.global.add.v4.f32 [%0], {%1,%2,%3,%4};"
                 :: "l"(p), "f"(v.x), "f"(v.y), "f"(v.z), "f"(v.w) : "memory");
}

// ---------------------------------------------------------------------------
// One-time: splat ones into both scalar normalizer tables.
__global__ void k_splat1(const float* __restrict__ wsB, const int* __restrict__ osB,
                         const float* __restrict__ wsS, const int* __restrict__ osS,
                         float* __restrict__ tB, float* __restrict__ tS) {
    int n = blockIdx.x * blockDim.x + threadIdx.x;
    if (n >= NPIX) return;
#pragma unroll
    for (int r = 0; r < RB; r++) atomicAdd(tB + osB[n * RB + r], wsB[n * RB + r]);
#pragma unroll
    for (int r = 0; r < RS; r++) atomicAdd(tS + osS[n * RS + r], wsS[n * RS + r]);
}

// ---------------------------------------------------------------------------
// Scalar blur pass over both lattices (spatial side optional). 1 vertex/thread.
__global__ void k_blur1_both(const float* __restrict__ inB, float* __restrict__ outB,
                             const int2* __restrict__ bnB, int Mb, int nBlkB,
                             const float* __restrict__ inS, float* __restrict__ outS,
                             const int2* __restrict__ bnS, int Ms) {
    int blk = blockIdx.x;
    const float* in; float* out; const int2* bn; int M;
    if (blk < nBlkB) { in = inB; out = outB; bn = bnB; M = Mb; }
    else { blk -= nBlkB; in = inS; out = outS; bn = bnS; M = Ms; }

    int i = blk * TPB + threadIdx.x;
    if (i == 0) out[0] = 0.f;
    if (i >= M) return;
    int2 nb = bn[i];
    float a = in[i + 1];
    float b = in[nb.x];
    float c = in[nb.y];
    out[i + 1] = a + 0.5f * (b + c);
}

// ---------------------------------------------------------------------------
// float4 blur pass over both lattices (1 vertex/thread), plus optional zeroing
// blocks that clear the next splat buffers (pass j==1; pass 0 consumed them).
__global__ void k_blur4_both(const float4* __restrict__ inB, float4* __restrict__ outB,
                             const int2* __restrict__ bnB, int Mb, int nBlkB,
                             const float4* __restrict__ inS, float4* __restrict__ outS,
                             const int2* __restrict__ bnS, int Ms, int nBlkS,
                             float4* __restrict__ z0, int nz0,
                             float4* __restrict__ z1, int nz1, int nBlkZ) {
    int blk = blockIdx.x;
    if (blk >= nBlkB + nBlkS) {
        int zb = blk - nBlkB - nBlkS;
        int stride = nBlkZ * TPB;
        const float4 zero = make_float4(0.f, 0.f, 0.f, 0.f);
        for (int i = zb * TPB + threadIdx.x; i < nz0; i += stride) z0[i] = zero;
        for (int i = zb * TPB + threadIdx.x; i < nz1; i += stride) z1[i] = zero;
        return;
    }
    const float4* in; float4* out; const int2* bn; int M;
    if (blk < nBlkB) { in = inB; out = outB; bn = bnB; M = Mb; }
    else { blk -= nBlkB; in = inS; out = outS; bn = bnS; M = Ms; }

    int i = blk * TPB + threadIdx.x;
    if (i == 0) out[0] = make_float4(0.f, 0.f, 0.f, 0.f);
    if (i >= M) return;
    int2 nb = bn[i];
    float4 a = in[i + 1];
    float4 b = in[nb.x];
    float4 c = in[nb.y];
    out[i + 1] = make_float4(a.x + 0.5f * (b.x + c.x),
                             a.y + 0.5f * (b.y + c.y),
                             a.z + 0.5f * (b.z + c.z),
                             a.w + 0.5f * (b.w + c.w));
}

// ---------------------------------------------------------------------------
// One-time: slice normalizer tables -> per-pixel message coefficients,
// then Q0 = softmax(-u) splatted directly into the float4 splat buffers.
__global__ void k_norm_init(const float* __restrict__ nBf, const float* __restrict__ nSf,
                            const float* __restrict__ wsB, const int* __restrict__ osB,
                            const float* __restrict__ wsS, const int* __restrict__ osS,
                            const float4* __restrict__ u4,
                            float* __restrict__ coefB, float* __restrict__ coefS,
                            float4* __restrict__ SB, float4* __restrict__ SS) {
    int n = blockIdx.x * blockDim.x + threadIdx.x;
    if (n >= NPIX) return;
    float sB = 0.f;
#pragma unroll
    for (int r = 0; r < RB; r++)
        sB = fmaf(nBf[osB[n * RB + r]], wsB[n * RB + r], sB);
    coefB[n] = 10.0f * ALPHA_B / (ALPHA_B * sB + 1e-20f);
    float sS = 0.f;
#pragma unroll
    for (int r = 0; r < RS; r++)
        sS = fmaf(nSf[osS[n * RS + r]], wsS[n * RS + r], sS);
    coefS[n] = 3.0f * ALPHA_S / (ALPHA_S * sS + 1e-20f);

    float4 u = u4[n];
    float x0 = -u.x, x1 = -u.y, x2 = -u.z, x3 = -u.w;
    float m = fmaxf(fmaxf(x0, x1), fmaxf(x2, x3));
    float e0 = __expf(x0 - m), e1 = __expf(x1 - m);
    float e2 = __expf(x2 - m), e3 = __expf(x3 - m);
    float inv = 1.0f / (e0 + e1 + e2 + e3);
    float4 q = make_float4(e0 * inv, e1 * inv, e2 * inv, e3 * inv);

#pragma unroll
    for (int r = 0; r < RB; r++) {
        float w = wsB[n * RB + r];
        red_v4(SB + osB[n * RB + r], make_float4(q.x * w, q.y * w, q.z * w, q.w * w));
    }
#pragma unroll
    for (int r = 0; r < RS; r++) {
        float w = wsS[n * RS + r];
        red_v4(SS + osS[n * RS + r], make_float4(q.x * w, q.y * w, q.z * w, q.w * w));
    }
}

// ---------------------------------------------------------------------------
// Per-iteration: slice both blurred tables, message + softmax, then either
// splat the new Q into the (pre-zeroed) splat buffers or write final output.
__global__ void k_fused(const float4* __restrict__ tB, const float4* __restrict__ tS,
                        const float* __restrict__ wsB, const int* __restrict__ osB,
                        const float* __restrict__ wsS, const int* __restrict__ osS,
                        const float* __restrict__ coefB, const float* __restrict__ coefS,
                        const float4* __restrict__ u4,
                        float4* __restrict__ SB, float4* __restrict__ SS,
                        float4* __restrict__ outQ, int write_out) {
    int n = blockIdx.x * blockDim.x + threadIdx.x;
    if (n >= NPIX) return;

    float4 fb = make_float4(0.f, 0.f, 0.f, 0.f);
#pragma unroll
    for (int r = 0; r < RB; r++) {
        float w = wsB[n * RB + r];
        float4 t = tB[osB[n * RB + r]];
        fb.x = fmaf(t.x, w, fb.x); fb.y = fmaf(t.y, w, fb.y);
        fb.z = fmaf(t.z, w, fb.z); fb.w = fmaf(t.w, w, fb.w);
    }
    float4 fs = make_float4(0.f, 0.f, 0.f, 0.f);
#pragma unroll
    for (int r = 0; r < RS; r++) {
        float w = wsS[n * RS + r];
        float4 t = tS[osS[n * RS + r]];
        fs.x = fmaf(t.x, w, fs.x); fs.y = fmaf(t.y, w, fs.y);
        fs.z = fmaf(t.z, w, fs.z); fs.w = fmaf(t.w, w, fs.w);
    }
    float cb = coefB[n];
    float cs = coefS[n];
    float4 u = u4[n];
    float x0 = fmaf(fb.x, cb, fmaf(fs.x, cs, -u.x));
    float x1 = fmaf(fb.y, cb, fmaf(fs.y, cs, -u.y));
    float x2 = fmaf(fb.z, cb, fmaf(fs.z, cs, -u.z));
    float x3 = fmaf(fb.w, cb, fmaf(fs.w, cs, -u.w));

    float m = fmaxf(fmaxf(x0, x1), fmaxf(x2, x3));
    float e0 = __expf(x0 - m), e1 = __expf(x1 - m);
    float e2 = __expf(x2 - m), e3 = __expf(x3 - m);
    float inv = 1.0f / (e0 + e1 + e2 + e3);
    float4 q = make_float4(e0 * inv, e1 * inv, e2 * inv, e3 * inv);

    if (write_out) {
        outQ[n] = q;
        return;
    }
#pragma unroll
    for (int r = 0; r < RB; r++) {
        float w = wsB[n * RB + r];
        red_v4(SB + osB[n * RB + r], make_float4(q.x * w, q.y * w, q.z * w, q.w * w));
    }
#pragma unroll
    for (int r = 0; r < RS; r++) {
        float w = wsS[n * RS + r];
        red_v4(SS + osS[n * RS + r], make_float4(q.x * w, q.y * w, q.z * w, q.w * w));
    }
}

// ---------------------------------------------------------------------------
extern "C" void kernel_launch(void* const* d_in, const int* in_sizes, int n_in,
                              void* d_out, int out_size) {
    const float4* u4  = (const float4*)d_in[0];
    const float*  wsB = (const float*)d_in[1];
    const int*    osB = (const int*)d_in[2];
    const int*    bnB = (const int*)d_in[3];
    const float*  wsS = (const float*)d_in[5];
    const int*    osS = (const int*)d_in[6];
    const int*    bnS = (const int*)d_in[7];

    const int Mb = in_sizes[3] / (2 * RB);
    const int Ms = in_sizes[7] / (2 * RS);

    float4 *SB, *PB, *SS, *PS;
    float *nB, *nS, *coefB, *coefS;
    cudaGetSymbolAddress((void**)&SB, g_SB);
    cudaGetSymbolAddress((void**)&PB, g_PB);
    cudaGetSymbolAddress((void**)&SS, g_SS);
    cudaGetSymbolAddress((void**)&PS, g_PS);
    cudaGetSymbolAddress((void**)&nB, g_nB);
    cudaGetSymbolAddress((void**)&nS, g_nS);
    cudaGetSymbolAddress((void**)&coefB, g_coefB);
    cudaGetSymbolAddress((void**)&coefS, g_coefS);
    float4* PBb[2] = { PB, PB + MAXVB };
    float4* PSb[2] = { PS, PS + MAXVS };
    float*  nBb[2] = { nB, nB + MAXVB };
    float*  nSb[2] = { nS, nS + MAXVS };

    const int GN    = (NPIX + TPB - 1) / TPB;
    const int nBlkB = (Mb + TPB - 1) / TPB;
    const int nBlkS = (Ms + TPB - 1) / TPB;
    const int nBlkZ = 128;

    // ---- one-time normalizer + init ----
    cudaMemsetAsync(nBb[0], 0, (size_t)(Mb + 1) * sizeof(float));
    cudaMemsetAsync(nSb[0], 0, (size_t)(Ms + 1) * sizeof(float));
    cudaMemsetAsync(SB, 0, (size_t)(Mb + 1) * sizeof(float4));
    cudaMemsetAsync(SS, 0, (size_t)(Ms + 1) * sizeof(float4));

    k_splat1<<<GN, TPB>>>(wsB, osB, wsS, osS, nBb[0], nSb[0]);
    for (int j = 0; j < RB; j++) {
        int sAct = (j < RS);
        k_blur1_both<<<nBlkB + (sAct ? nBlkS : 0), TPB>>>(
            nBb[j & 1], nBb[(j + 1) & 1], (const int2*)(bnB + (size_t)j * 2 * Mb), Mb, nBlkB,
            sAct ? nSb[j & 1] : nullptr, sAct ? nSb[(j + 1) & 1] : nullptr,
            sAct ? (const int2*)(bnS + (size_t)j * 2 * Ms) : nullptr, sAct ? Ms : 0);
    }
    // bilateral final in nBb[0] (6 passes), spatial final in nSb[1] (3 passes)
    k_norm_init<<<GN, TPB>>>(nBb[0], nSb[1], wsB, osB, wsS, osS, u4,
                             coefB, coefS, SB, SS);

    // ---- 10 mean-field iterations ----
    for (int it = 0; it < 10; it++) {
        for (int j = 0; j < RB; j++) {
            int sAct = (j < RS);
            const float4* ib = (j == 0) ? SB : PBb[(j - 1) & 1];
            float4* ob = PBb[j & 1];
            const float4* is = (j == 0) ? SS : PSb[(j - 1) & 1];
            float4* osp = PSb[j & 1];
            int zBlk = (j == 1) ? nBlkZ : 0;
            k_blur4_both<<<nBlkB + (sAct ? nBlkS : 0) + zBlk, TPB>>>(
                ib, ob, (const int2*)(bnB + (size_t)j * 2 * Mb), Mb, nBlkB,
                sAct ? is : nullptr, sAct ? osp : nullptr,
                sAct ? (const int2*)(bnS + (size_t)j * 2 * Ms) : nullptr,
                sAct ? Ms : 0, sAct ? nBlkS : 0,
                SB, Mb + 1, SS, Ms + 1, nBlkZ);
        }
        // bilateral final PBb[1], spatial final PSb[0]
        k_fused<<<GN, TPB>>>(PBb[1], PSb[0], wsB, osB, wsS, osS,
                             coefB, coefS, u4, SB, SS,
                             (float4*)d_out, (it == 9) ? 1 : 0);
    }
}